// round 1
// baseline (speedup 1.0000x reference)
#include <cuda_runtime.h>
#include <cuda_bf16.h>
#include <cstdint>

#define EMB    512
#define HID    512
#define NCLASS 50257
#define BATCH  64
#define STEPS  256
#define FOURH  2048

// ---------------- scratch (device globals; no mallocs allowed) ---------------
__device__ float    g_xw[STEPS * BATCH * FOURH];   // 128 MiB precomputed input proj
__device__ float    g_h[2 * BATCH * HID];          // double-buffered hidden state
__device__ float    g_bsum[FOURH];                 // bi + bh
__device__ unsigned g_barc;                        // grid barrier count
__device__ unsigned g_barp;                        // grid barrier phase (monotonic)

// ---------------- packed f32x2 helpers (sm_103a) ------------------------------
__device__ __forceinline__ unsigned long long pack2(float x, float y) {
    unsigned long long r;
    asm("mov.b64 %0, {%1, %2};" : "=l"(r) : "f"(x), "f"(y));
    return r;
}
__device__ __forceinline__ void fma2(unsigned long long& acc,
                                     unsigned long long a, unsigned long long b) {
    asm("fma.rn.f32x2 %0, %1, %2, %0;" : "+l"(acc) : "l"(a), "l"(b));
}
__device__ __forceinline__ float2 unpack2(unsigned long long v) {
    float2 f;
    asm("mov.b64 {%0, %1}, %2;" : "=f"(f.x), "=f"(f.y) : "l"(v));
    return f;
}
__device__ __forceinline__ float hsum2(unsigned long long v) {
    float2 f = unpack2(v);
    return f.x + f.y;
}
__device__ __forceinline__ float sigmoidf_(float x) {
    return 1.0f / (1.0f + expf(-x));
}

// ---------------- grid barrier -------------------------------------------------
__device__ __forceinline__ void grid_barrier(unsigned nct) {
    __syncthreads();
    if (threadIdx.x == 0) {
        volatile unsigned* vp = &g_barp;
        unsigned ph = *vp;
        __threadfence();
        unsigned old = atomicAdd(&g_barc, 1u);
        if (old == nct - 1u) {
            g_barc = 0u;
            __threadfence();
            atomicAdd(&g_barp, 1u);
        } else {
            while (*vp == ph) { __nanosleep(64); }
        }
        __threadfence();
    }
    __syncthreads();
}

// ---------------- kernel 0: prep (bsum = bi + bh, zero h) ---------------------
__global__ void prep_kernel(const float* __restrict__ bi, const float* __restrict__ bh) {
    int i = blockIdx.x * blockDim.x + threadIdx.x;
    int stride = gridDim.x * blockDim.x;
    if (i < FOURH) g_bsum[i] = bi[i] + bh[i];
    for (int j = i; j < 2 * BATCH * HID; j += stride) g_h[j] = 0.0f;
}

// ---------------- kernel 1: xw = gather(emb, X) @ Wi + bsum -------------------
// C[16384, 2048], K = 512. BM=BN=128, BK=16, 256 threads, 8x8 microtile, f32x2.
__global__ __launch_bounds__(256, 2) void xw_gemm_kernel(
    const int* __restrict__ X, const float* __restrict__ emb,
    const float* __restrict__ Wi) {
    __shared__ float As[16][132];  // A^T tile: As[k][m]
    __shared__ float Bs[16][132];  // Bs[k][n]
    __shared__ int   tok[128];

    const int tid = threadIdx.x;
    const int m0 = blockIdx.y * 128;
    const int n0 = blockIdx.x * 128;
    const int tm = tid >> 4, tn = tid & 15;

    if (tid < 128) {
        int m = m0 + tid;
        int b = m & 63, t = m >> 6;
        tok[tid] = X[b * STEPS + t];
    }

    unsigned long long acc[8][4];
#pragma unroll
    for (int i = 0; i < 8; ++i)
#pragma unroll
        for (int j = 0; j < 4; ++j) acc[i][j] = 0ull;

    for (int kt = 0; kt < EMB; kt += 16) {
        __syncthreads();
        // A tile: 128 rows x 16 k (gathered embedding rows), transposed into smem
#pragma unroll
        for (int q = 0; q < 2; ++q) {
            int id = tid + q * 256;           // 0..511 float4 slots
            int row = id >> 2, c4 = id & 3;
            const float4 v = *(const float4*)(emb + (size_t)tok[row] * EMB + kt + c4 * 4);
            As[c4 * 4 + 0][row] = v.x;
            As[c4 * 4 + 1][row] = v.y;
            As[c4 * 4 + 2][row] = v.z;
            As[c4 * 4 + 3][row] = v.w;
        }
        // B tile: Wi[kt..kt+16][n0..n0+128]
#pragma unroll
        for (int q = 0; q < 2; ++q) {
            int id = tid + q * 256;
            int k = id >> 5, c4 = id & 31;
            const float4 v = *(const float4*)(Wi + (size_t)(kt + k) * FOURH + n0 + c4 * 4);
            *(float4*)&Bs[k][c4 * 4] = v;
        }
        __syncthreads();
#pragma unroll
        for (int kk = 0; kk < 16; ++kk) {
            float4 a0 = *(const float4*)&As[kk][tm * 8];
            float4 a1 = *(const float4*)&As[kk][tm * 8 + 4];
            float4 b0 = *(const float4*)&Bs[kk][tn * 8];
            float4 b1 = *(const float4*)&Bs[kk][tn * 8 + 4];
            unsigned long long bp0 = ((const unsigned long long*)&b0)[0];
            unsigned long long bp1 = ((const unsigned long long*)&b0)[1];
            unsigned long long bp2 = ((const unsigned long long*)&b1)[0];
            unsigned long long bp3 = ((const unsigned long long*)&b1)[1];
            float av[8] = {a0.x, a0.y, a0.z, a0.w, a1.x, a1.y, a1.z, a1.w};
#pragma unroll
            for (int i = 0; i < 8; ++i) {
                unsigned long long ad = pack2(av[i], av[i]);
                fma2(acc[i][0], ad, bp0);
                fma2(acc[i][1], ad, bp1);
                fma2(acc[i][2], ad, bp2);
                fma2(acc[i][3], ad, bp3);
            }
        }
    }

    // epilogue: add bsum, store
    const float4 bs0 = *(const float4*)&g_bsum[n0 + tn * 8];
    const float4 bs1 = *(const float4*)&g_bsum[n0 + tn * 8 + 4];
    const float bsv[8] = {bs0.x, bs0.y, bs0.z, bs0.w, bs1.x, bs1.y, bs1.z, bs1.w};
#pragma unroll
    for (int i = 0; i < 8; ++i) {
        int m = m0 + tm * 8 + i;
        float o[8];
#pragma unroll
        for (int j = 0; j < 4; ++j) {
            float2 v = unpack2(acc[i][j]);
            o[2 * j] = v.x + bsv[2 * j];
            o[2 * j + 1] = v.y + bsv[2 * j + 1];
        }
        float* orow = g_xw + (size_t)m * FOURH + n0 + tn * 8;
        *(float4*)&orow[0] = make_float4(o[0], o[1], o[2], o[3]);
        *(float4*)&orow[4] = make_float4(o[4], o[5], o[6], o[7]);
    }
}

// ---------------- kernel 2: persistent LSTM recurrence ------------------------
// 128 CTAs x 256 thr. CTA owns 4 hidden units (16 gate cols). One grid barrier/step.
__global__ __launch_bounds__(256, 1) void lstm_kernel(const float* __restrict__ Wh) {
    __shared__ float sw[16][514];   // Wh columns for this CTA: sw[c][k]
    __shared__ float sh[64][36];    // h k-tile (KT=32)
    __shared__ float spre[16][65];  // pre-activations [c][b]
    __shared__ float sc[256];       // cell state [b*4+u]

    const int tid = threadIdx.x;
    const int cta = blockIdx.x;
    const unsigned nct = gridDim.x;

    // one-time load of the 16 Wh columns this CTA owns (col = g*512 + cta*4 + u)
    for (int i = tid; i < 16 * HID; i += 256) {
        int c = i >> 9, k = i & 511;
        int g = c >> 2, u = c & 3;
        sw[c][k] = Wh[(size_t)k * FOURH + g * HID + cta * 4 + u];
    }
    sc[tid] = 0.0f;

    const int cp = tid & 7, bp = tid >> 3;
    const int b0 = 2 * bp, b1 = b0 + 1;
    const int c0 = 2 * cp, c1 = c0 + 1;
    const int gc0 = (c0 >> 2) * HID + cta * 4 + (c0 & 3);
    const int gc1 = (c1 >> 2) * HID + cta * 4 + (c1 & 3);

    // coop-load ids for h tiles: 64 rows x 32 floats = 512 float4, 2 per thread
    const int lr0 = tid >> 3, lc0 = (tid & 7) * 4;
    const int lr1 = (tid + 256) >> 3, lc1 = ((tid + 256) & 7) * 4;

    const int upd_u = tid & 3, upd_b = tid >> 2;

    __syncthreads();

    for (int t = 0; t < STEPS; ++t) {
        const float* hin = g_h + (t & 1) * BATCH * HID;
        float* hout = g_h + ((t + 1) & 1) * BATCH * HID;

        unsigned long long a00 = 0, a01 = 0, a10 = 0, a11 = 0;

        // prefetch tile 0
        float4 p0 = __ldcg((const float4*)(hin + lr0 * HID + lc0));
        float4 p1 = __ldcg((const float4*)(hin + lr1 * HID + lc1));

        for (int kt = 0; kt < HID; kt += 32) {
            __syncthreads();  // sh free
            *(float4*)&sh[lr0][lc0] = p0;
            *(float4*)&sh[lr1][lc1] = p1;
            if (kt + 32 < HID) {
                p0 = __ldcg((const float4*)(hin + lr0 * HID + kt + 32 + lc0));
                p1 = __ldcg((const float4*)(hin + lr1 * HID + kt + 32 + lc1));
            }
            __syncthreads();  // sh ready
#pragma unroll
            for (int kk = 0; kk < 32; kk += 2) {
                unsigned long long h0 = *(const unsigned long long*)&sh[b0][kk];
                unsigned long long h1 = *(const unsigned long long*)&sh[b1][kk];
                unsigned long long w0 = *(const unsigned long long*)&sw[c0][kt + kk];
                unsigned long long w1 = *(const unsigned long long*)&sw[c1][kt + kk];
                fma2(a00, h0, w0);
                fma2(a01, h0, w1);
                fma2(a10, h1, w0);
                fma2(a11, h1, w1);
            }
        }

        const float* xwt = g_xw + (size_t)t * BATCH * FOURH;
        spre[c0][b0] = hsum2(a00) + __ldg(&xwt[b0 * FOURH + gc0]);
        spre[c1][b0] = hsum2(a01) + __ldg(&xwt[b0 * FOURH + gc1]);
        spre[c0][b1] = hsum2(a10) + __ldg(&xwt[b1 * FOURH + gc0]);
        spre[c1][b1] = hsum2(a11) + __ldg(&xwt[b1 * FOURH + gc1]);
        __syncthreads();

        // cell update: thread -> (b = tid>>2, u = tid&3)
        {
            float pi = spre[0 + upd_u][upd_b];
            float pf = spre[4 + upd_u][upd_b];
            float pg = spre[8 + upd_u][upd_b];
            float po = spre[12 + upd_u][upd_b];
            float ig = sigmoidf_(pi);
            float fg = sigmoidf_(pf);
            float gg = tanhf(pg);
            float og = sigmoidf_(po);
            float cc = fg * sc[tid] + ig * gg;
            sc[tid] = cc;
            float hh = og * tanhf(cc);
            __stcg(&hout[upd_b * HID + cta * 4 + upd_u], hh);
        }
        grid_barrier(nct);
    }
}

// ---------------- kernel 3: out = h_final @ Wout^T + bout ---------------------
// C[n, b] tiles: BM=128 n-rows, all 64 b, BK=16. 256 thr, 8n x 4b microtile.
__global__ __launch_bounds__(256, 2) void outproj_kernel(
    const float* __restrict__ Wout, const float* __restrict__ bout,
    float* __restrict__ out) {
    __shared__ float As[16][132];  // Wout^T tile: As[k][n_local]
    __shared__ float Bs[16][68];   // h^T tile:   Bs[k][b]

    const int tid = threadIdx.x;
    const int n0 = blockIdx.x * 128;
    const int tn = tid & 15, tb = tid >> 4;
    const float* h = g_h;  // final h lives in buffer 0 (STEPS even)

    unsigned long long acc[8][2];
#pragma unroll
    for (int i = 0; i < 8; ++i) { acc[i][0] = 0ull; acc[i][1] = 0ull; }

    for (int kt = 0; kt < HID; kt += 16) {
        __syncthreads();
#pragma unroll
        for (int q = 0; q < 2; ++q) {
            int id = tid + q * 256;
            int row = id >> 2, c4 = id & 3;
            int n = n0 + row;
            float4 v = make_float4(0.f, 0.f, 0.f, 0.f);
            if (n < NCLASS) v = *(const float4*)(Wout + (size_t)n * HID + kt + c4 * 4);
            As[c4 * 4 + 0][row] = v.x;
            As[c4 * 4 + 1][row] = v.y;
            As[c4 * 4 + 2][row] = v.z;
            As[c4 * 4 + 3][row] = v.w;
        }
#pragma unroll
        for (int q = 0; q < 4; ++q) {
            int id = tid + q * 256;   // 0..1023
            int b = id >> 4, k = id & 15;
            Bs[k][b] = h[b * HID + kt + k];
        }
        __syncthreads();
#pragma unroll
        for (int kk = 0; kk < 16; ++kk) {
            float4 a0 = *(const float4*)&As[kk][tn * 8];
            float4 a1 = *(const float4*)&As[kk][tn * 8 + 4];
            float4 bv = *(const float4*)&Bs[kk][tb * 4];
            unsigned long long bp0 = ((const unsigned long long*)&bv)[0];
            unsigned long long bp1 = ((const unsigned long long*)&bv)[1];
            float av[8] = {a0.x, a0.y, a0.z, a0.w, a1.x, a1.y, a1.z, a1.w};
#pragma unroll
            for (int i = 0; i < 8; ++i) {
                unsigned long long ad = pack2(av[i], av[i]);
                fma2(acc[i][0], ad, bp0);
                fma2(acc[i][1], ad, bp1);
            }
        }
    }

#pragma unroll
    for (int i = 0; i < 8; ++i) {
        int n = n0 + tn * 8 + i;
        if (n >= NCLASS) continue;
        float bo = bout[n];
        float2 v0 = unpack2(acc[i][0]);
        float2 v1 = unpack2(acc[i][1]);
        out[(size_t)(tb * 4 + 0) * NCLASS + n] = v0.x + bo;
        out[(size_t)(tb * 4 + 1) * NCLASS + n] = v0.y + bo;
        out[(size_t)(tb * 4 + 2) * NCLASS + n] = v1.x + bo;
        out[(size_t)(tb * 4 + 3) * NCLASS + n] = v1.y + bo;
    }
}

// ---------------- launch --------------------------------------------------------
extern "C" void kernel_launch(void* const* d_in, const int* in_sizes, int n_in,
                              void* d_out, int out_size) {
    const int*   X    = (const int*)d_in[0];
    const float* emb  = (const float*)d_in[1];
    const float* Wi   = (const float*)d_in[2];
    const float* Wh   = (const float*)d_in[3];
    const float* bi   = (const float*)d_in[4];
    const float* bh   = (const float*)d_in[5];
    // d_in[6..9]: layer-2 params — provably unused by the reference output
    const float* Wout = (const float*)d_in[10];
    const float* bout = (const float*)d_in[11];
    float* out = (float*)d_out;

    prep_kernel<<<64, 256>>>(bi, bh);
    xw_gemm_kernel<<<dim3(FOURH / 128, (STEPS * BATCH) / 128), 256>>>(X, emb, Wi);
    lstm_kernel<<<128, 256>>>(Wh);
    outproj_kernel<<<(NCLASS + 127) / 128, 256>>>(Wout, bout, out);
}

// round 2
// speedup vs baseline: 1.0937x; 1.0937x over previous
#include <cuda_runtime.h>
#include <cuda_bf16.h>
#include <cstdint>

#define EMB    512
#define HID    512
#define NCLASS 50257
#define BATCH  64
#define STEPS  256
#define FOURH  2048

// ---------------- scratch (device globals; no mallocs allowed) ---------------
__device__ float    g_xw[STEPS * BATCH * FOURH];   // 128 MiB precomputed input proj
__device__ float    g_h[2 * BATCH * HID];          // double-buffered hidden state
__device__ float    g_bsum[FOURH];                 // bi + bh
__device__ unsigned g_barc;                        // grid barrier count
__device__ unsigned g_barp;                        // grid barrier phase (monotonic)

// ---------------- packed f32x2 helpers (sm_103a) ------------------------------
__device__ __forceinline__ unsigned long long pack2(float x, float y) {
    unsigned long long r;
    asm("mov.b64 %0, {%1, %2};" : "=l"(r) : "f"(x), "f"(y));
    return r;
}
__device__ __forceinline__ void fma2(unsigned long long& acc,
                                     unsigned long long a, unsigned long long b) {
    asm("fma.rn.f32x2 %0, %1, %2, %0;" : "+l"(acc) : "l"(a), "l"(b));
}
__device__ __forceinline__ float2 unpack2(unsigned long long v) {
    float2 f;
    asm("mov.b64 {%0, %1}, %2;" : "=f"(f.x), "=f"(f.y) : "l"(v));
    return f;
}
__device__ __forceinline__ float hsum2(unsigned long long v) {
    float2 f = unpack2(v);
    return f.x + f.y;
}
__device__ __forceinline__ float sigmoidf_(float x) {
    return 1.0f / (1.0f + expf(-x));
}
__device__ __forceinline__ unsigned long long f4lo(const float4& v) {
    return ((const unsigned long long*)&v)[0];
}
__device__ __forceinline__ unsigned long long f4hi(const float4& v) {
    return ((const unsigned long long*)&v)[1];
}

// ---------------- grid barrier (tight spin, release/acquire via fences) -------
__device__ __forceinline__ void grid_barrier(unsigned nct) {
    __syncthreads();
    if (threadIdx.x == 0) {
        volatile unsigned* vp = &g_barp;
        unsigned ph = *vp;
        __threadfence();
        unsigned old = atomicAdd(&g_barc, 1u);
        if (old == nct - 1u) {
            g_barc = 0u;
            __threadfence();
            atomicAdd(&g_barp, 1u);
        } else {
            while (*vp == ph) {}
        }
        __threadfence();
    }
    __syncthreads();
}

// ---------------- kernel 0: prep (bsum = bi + bh, zero h) ---------------------
__global__ void prep_kernel(const float* __restrict__ bi, const float* __restrict__ bh) {
    int i = blockIdx.x * blockDim.x + threadIdx.x;
    int stride = gridDim.x * blockDim.x;
    if (i < FOURH) g_bsum[i] = bi[i] + bh[i];
    for (int j = i; j < 2 * BATCH * HID; j += stride) g_h[j] = 0.0f;
}

// ---------------- kernel 1: xw = gather(emb, X) @ Wi + bsum -------------------
// C[16384, 2048], K = 512. BM=BN=128, BK=16, 256 threads, 8x8 microtile, f32x2.
__global__ __launch_bounds__(256, 2) void xw_gemm_kernel(
    const int* __restrict__ X, const float* __restrict__ emb,
    const float* __restrict__ Wi) {
    __shared__ float As[16][132];  // A^T tile: As[k][m]
    __shared__ float Bs[16][132];  // Bs[k][n]
    __shared__ int   tok[128];

    const int tid = threadIdx.x;
    const int m0 = blockIdx.y * 128;
    const int n0 = blockIdx.x * 128;
    const int tm = tid >> 4, tn = tid & 15;

    if (tid < 128) {
        int m = m0 + tid;
        int b = m & 63, t = m >> 6;
        tok[tid] = X[b * STEPS + t];
    }

    unsigned long long acc[8][4];
#pragma unroll
    for (int i = 0; i < 8; ++i)
#pragma unroll
        for (int j = 0; j < 4; ++j) acc[i][j] = 0ull;

    for (int kt = 0; kt < EMB; kt += 16) {
        __syncthreads();
#pragma unroll
        for (int q = 0; q < 2; ++q) {
            int id = tid + q * 256;           // 0..511 float4 slots
            int row = id >> 2, c4 = id & 3;
            const float4 v = *(const float4*)(emb + (size_t)tok[row] * EMB + kt + c4 * 4);
            As[c4 * 4 + 0][row] = v.x;
            As[c4 * 4 + 1][row] = v.y;
            As[c4 * 4 + 2][row] = v.z;
            As[c4 * 4 + 3][row] = v.w;
        }
#pragma unroll
        for (int q = 0; q < 2; ++q) {
            int id = tid + q * 256;
            int k = id >> 5, c4 = id & 31;
            const float4 v = *(const float4*)(Wi + (size_t)(kt + k) * FOURH + n0 + c4 * 4);
            *(float4*)&Bs[k][c4 * 4] = v;
        }
        __syncthreads();
#pragma unroll
        for (int kk = 0; kk < 16; ++kk) {
            float4 a0 = *(const float4*)&As[kk][tm * 8];
            float4 a1 = *(const float4*)&As[kk][tm * 8 + 4];
            float4 b0 = *(const float4*)&Bs[kk][tn * 8];
            float4 b1 = *(const float4*)&Bs[kk][tn * 8 + 4];
            unsigned long long bp0 = ((const unsigned long long*)&b0)[0];
            unsigned long long bp1 = ((const unsigned long long*)&b0)[1];
            unsigned long long bp2 = ((const unsigned long long*)&b1)[0];
            unsigned long long bp3 = ((const unsigned long long*)&b1)[1];
            float av[8] = {a0.x, a0.y, a0.z, a0.w, a1.x, a1.y, a1.z, a1.w};
#pragma unroll
            for (int i = 0; i < 8; ++i) {
                unsigned long long ad = pack2(av[i], av[i]);
                fma2(acc[i][0], ad, bp0);
                fma2(acc[i][1], ad, bp1);
                fma2(acc[i][2], ad, bp2);
                fma2(acc[i][3], ad, bp3);
            }
        }
    }

    const float4 bs0 = *(const float4*)&g_bsum[n0 + tn * 8];
    const float4 bs1 = *(const float4*)&g_bsum[n0 + tn * 8 + 4];
    const float bsv[8] = {bs0.x, bs0.y, bs0.z, bs0.w, bs1.x, bs1.y, bs1.z, bs1.w};
#pragma unroll
    for (int i = 0; i < 8; ++i) {
        int m = m0 + tm * 8 + i;
        float o[8];
#pragma unroll
        for (int j = 0; j < 4; ++j) {
            float2 v = unpack2(acc[i][j]);
            o[2 * j] = v.x + bsv[2 * j];
            o[2 * j + 1] = v.y + bsv[2 * j + 1];
        }
        float* orow = g_xw + (size_t)m * FOURH + n0 + tn * 8;
        *(float4*)&orow[0] = make_float4(o[0], o[1], o[2], o[3]);
        *(float4*)&orow[4] = make_float4(o[4], o[5], o[6], o[7]);
    }
}

// ---------------- kernel 2: persistent LSTM recurrence ------------------------
// 128 CTAs x 256 thr. CTA owns 4 hidden units (16 gate cols). One grid barrier/step.
// k-vec4 (LDS.128), double-buffered 64-wide h tiles (8 syncs/step), prefetched xw.
__global__ __launch_bounds__(256, 1) void lstm_kernel(const float* __restrict__ Wh) {
    __shared__ __align__(16) float swE[8][516];   // even gate-cols, stride 516 (cp*4 banks)
    __shared__ __align__(16) float swO[8][516];   // odd  gate-cols
    __shared__ __align__(16) float sh[2][64][68]; // double-buffered h k-tiles
    __shared__ float spre[16][65];                // pre-activations [c][b]
    __shared__ float sc[256];                     // cell state [b*4+u]

    const int tid = threadIdx.x;
    const int cta = blockIdx.x;
    const unsigned nct = gridDim.x;

    // one-time load of the 16 Wh columns this CTA owns (col = g*512 + cta*4 + u)
    for (int i = tid; i < 16 * HID; i += 256) {
        int c = i >> 9, k = i & 511;
        int g = c >> 2, u = c & 3;
        float w = Wh[(size_t)k * FOURH + g * HID + cta * 4 + u];
        if (c & 1) swO[c >> 1][k] = w;
        else       swE[c >> 1][k] = w;
    }
    sc[tid] = 0.0f;

    const int cp = tid & 7, bp = tid >> 3;
    const int b0 = 2 * bp, b1 = b0 + 1;
    const int c0 = 2 * cp, c1 = c0 + 1;
    const int gc0 = (c0 >> 2) * HID + cta * 4 + (c0 & 3);
    const int gc1 = (c1 >> 2) * HID + cta * 4 + (c1 & 3);

    // cooperative-load mapping: 64 rows x 64 k floats = 1024 float4; 4 per thread
    const int lrow = tid >> 4;        // 0..15 (+16q)
    const int lcol = (tid & 15) * 4;  // float offset within tile

    const int upd_u = tid & 3, upd_b = tid >> 2;

    __syncthreads();

    for (int t = 0; t < STEPS; ++t) {
        const float* hin  = g_h + (t & 1) * BATCH * HID;
        float*       hout = g_h + ((t + 1) & 1) * BATCH * HID;
        const float* xwt  = g_xw + (size_t)t * BATCH * FOURH;

        // prefetch xw gate biases for this step (DRAM; hidden behind the GEMM)
        float x00 = __ldcs(&xwt[b0 * FOURH + gc0]);
        float x01 = __ldcs(&xwt[b0 * FOURH + gc1]);
        float x10 = __ldcs(&xwt[b1 * FOURH + gc0]);
        float x11 = __ldcs(&xwt[b1 * FOURH + gc1]);

        unsigned long long a00a = 0, a00b = 0, a01a = 0, a01b = 0;
        unsigned long long a10a = 0, a10b = 0, a11a = 0, a11b = 0;

        // tile 0 -> sh[0], prefetch tile 1 into regs
        float4 p0 = __ldcg((const float4*)(hin + (lrow + 0)  * HID + lcol));
        float4 p1 = __ldcg((const float4*)(hin + (lrow + 16) * HID + lcol));
        float4 p2 = __ldcg((const float4*)(hin + (lrow + 32) * HID + lcol));
        float4 p3 = __ldcg((const float4*)(hin + (lrow + 48) * HID + lcol));
        *(float4*)&sh[0][lrow + 0][lcol]  = p0;
        *(float4*)&sh[0][lrow + 16][lcol] = p1;
        *(float4*)&sh[0][lrow + 32][lcol] = p2;
        *(float4*)&sh[0][lrow + 48][lcol] = p3;
        p0 = __ldcg((const float4*)(hin + (lrow + 0)  * HID + 64 + lcol));
        p1 = __ldcg((const float4*)(hin + (lrow + 16) * HID + 64 + lcol));
        p2 = __ldcg((const float4*)(hin + (lrow + 32) * HID + 64 + lcol));
        p3 = __ldcg((const float4*)(hin + (lrow + 48) * HID + 64 + lcol));
        __syncthreads();

        for (int kt8 = 0; kt8 < 8; ++kt8) {
            const float* shb = &sh[kt8 & 1][0][0];
            const float* hrow0 = shb + b0 * 68;
            const float* hrow1 = shb + b1 * 68;
            const float* wrow0 = &swE[cp][kt8 * 64];
            const float* wrow1 = &swO[cp][kt8 * 64];
#pragma unroll
            for (int kk = 0; kk < 64; kk += 4) {
                float4 h0 = *(const float4*)(hrow0 + kk);
                float4 h1 = *(const float4*)(hrow1 + kk);
                float4 w0 = *(const float4*)(wrow0 + kk);
                float4 w1 = *(const float4*)(wrow1 + kk);
                unsigned long long h0a = f4lo(h0), h0b = f4hi(h0);
                unsigned long long h1a = f4lo(h1), h1b = f4hi(h1);
                unsigned long long w0a = f4lo(w0), w0b = f4hi(w0);
                unsigned long long w1a = f4lo(w1), w1b = f4hi(w1);
                fma2(a00a, h0a, w0a); fma2(a00b, h0b, w0b);
                fma2(a01a, h0a, w1a); fma2(a01b, h0b, w1b);
                fma2(a10a, h1a, w0a); fma2(a10b, h1b, w0b);
                fma2(a11a, h1a, w1a); fma2(a11b, h1b, w1b);
            }
            if (kt8 < 7) {
                int nb = (kt8 + 1) & 1;
                *(float4*)&sh[nb][lrow + 0][lcol]  = p0;
                *(float4*)&sh[nb][lrow + 16][lcol] = p1;
                *(float4*)&sh[nb][lrow + 32][lcol] = p2;
                *(float4*)&sh[nb][lrow + 48][lcol] = p3;
                if (kt8 < 6) {
                    int ko = (kt8 + 2) * 64;
                    p0 = __ldcg((const float4*)(hin + (lrow + 0)  * HID + ko + lcol));
                    p1 = __ldcg((const float4*)(hin + (lrow + 16) * HID + ko + lcol));
                    p2 = __ldcg((const float4*)(hin + (lrow + 32) * HID + ko + lcol));
                    p3 = __ldcg((const float4*)(hin + (lrow + 48) * HID + ko + lcol));
                }
                __syncthreads();
            }
        }

        spre[c0][b0] = hsum2(a00a) + hsum2(a00b) + x00;
        spre[c1][b0] = hsum2(a01a) + hsum2(a01b) + x01;
        spre[c0][b1] = hsum2(a10a) + hsum2(a10b) + x10;
        spre[c1][b1] = hsum2(a11a) + hsum2(a11b) + x11;
        __syncthreads();

        // cell update: thread -> (b = tid>>2, u = tid&3)
        {
            float pi = spre[0  + upd_u][upd_b];
            float pf = spre[4  + upd_u][upd_b];
            float pg = spre[8  + upd_u][upd_b];
            float po = spre[12 + upd_u][upd_b];
            float ig = sigmoidf_(pi);
            float fg = sigmoidf_(pf);
            float gg = tanhf(pg);
            float og = sigmoidf_(po);
            float cc = fg * sc[tid] + ig * gg;
            sc[tid] = cc;
            float hh = og * tanhf(cc);
            __stcg(&hout[upd_b * HID + cta * 4 + upd_u], hh);
        }
        grid_barrier(nct);
    }
}

// ---------------- kernel 3: out = h_final @ Wout^T + bout ---------------------
__global__ __launch_bounds__(256, 2) void outproj_kernel(
    const float* __restrict__ Wout, const float* __restrict__ bout,
    float* __restrict__ out) {
    __shared__ float As[16][132];  // Wout^T tile: As[k][n_local]
    __shared__ float Bs[16][68];   // h^T tile:   Bs[k][b]

    const int tid = threadIdx.x;
    const int n0 = blockIdx.x * 128;
    const int tn = tid & 15, tb = tid >> 4;
    const float* h = g_h;  // final h lives in buffer 0 (STEPS even)

    unsigned long long acc[8][2];
#pragma unroll
    for (int i = 0; i < 8; ++i) { acc[i][0] = 0ull; acc[i][1] = 0ull; }

    for (int kt = 0; kt < HID; kt += 16) {
        __syncthreads();
#pragma unroll
        for (int q = 0; q < 2; ++q) {
            int id = tid + q * 256;
            int row = id >> 2, c4 = id & 3;
            int n = n0 + row;
            float4 v = make_float4(0.f, 0.f, 0.f, 0.f);
            if (n < NCLASS) v = *(const float4*)(Wout + (size_t)n * HID + kt + c4 * 4);
            As[c4 * 4 + 0][row] = v.x;
            As[c4 * 4 + 1][row] = v.y;
            As[c4 * 4 + 2][row] = v.z;
            As[c4 * 4 + 3][row] = v.w;
        }
#pragma unroll
        for (int q = 0; q < 4; ++q) {
            int id = tid + q * 256;   // 0..1023
            int b = id >> 4, k = id & 15;
            Bs[k][b] = h[b * HID + kt + k];
        }
        __syncthreads();
#pragma unroll
        for (int kk = 0; kk < 16; ++kk) {
            float4 a0 = *(const float4*)&As[kk][tn * 8];
            float4 a1 = *(const float4*)&As[kk][tn * 8 + 4];
            float4 bv = *(const float4*)&Bs[kk][tb * 4];
            unsigned long long bp0 = ((const unsigned long long*)&bv)[0];
            unsigned long long bp1 = ((const unsigned long long*)&bv)[1];
            float av[8] = {a0.x, a0.y, a0.z, a0.w, a1.x, a1.y, a1.z, a1.w};
#pragma unroll
            for (int i = 0; i < 8; ++i) {
                unsigned long long ad = pack2(av[i], av[i]);
                fma2(acc[i][0], ad, bp0);
                fma2(acc[i][1], ad, bp1);
            }
        }
    }

#pragma unroll
    for (int i = 0; i < 8; ++i) {
        int n = n0 + tn * 8 + i;
        if (n >= NCLASS) continue;
        float bo = bout[n];
        float2 v0 = unpack2(acc[i][0]);
        float2 v1 = unpack2(acc[i][1]);
        out[(size_t)(tb * 4 + 0) * NCLASS + n] = v0.x + bo;
        out[(size_t)(tb * 4 + 1) * NCLASS + n] = v0.y + bo;
        out[(size_t)(tb * 4 + 2) * NCLASS + n] = v1.x + bo;
        out[(size_t)(tb * 4 + 3) * NCLASS + n] = v1.y + bo;
    }
}

// ---------------- launch --------------------------------------------------------
extern "C" void kernel_launch(void* const* d_in, const int* in_sizes, int n_in,
                              void* d_out, int out_size) {
    const int*   X    = (const int*)d_in[0];
    const float* emb  = (const float*)d_in[1];
    const float* Wi   = (const float*)d_in[2];
    const float* Wh   = (const float*)d_in[3];
    const float* bi   = (const float*)d_in[4];
    const float* bh   = (const float*)d_in[5];
    // d_in[6..9]: layer-2 params — provably unused by the reference output
    const float* Wout = (const float*)d_in[10];
    const float* bout = (const float*)d_in[11];
    float* out = (float*)d_out;

    prep_kernel<<<64, 256>>>(bi, bh);
    xw_gemm_kernel<<<dim3(FOURH / 128, (STEPS * BATCH) / 128), 256>>>(X, emb, Wi);
    lstm_kernel<<<128, 256>>>(Wh);
    outproj_kernel<<<(NCLASS + 127) / 128, 256>>>(Wout, bout, out);
}